// round 1
// baseline (speedup 1.0000x reference)
#include <cuda_runtime.h>
#include <cuda_bf16.h>

// Problem constants
#define T_LEN  4096
#define NB     32
#define NU     64
#define NY     64
#define NH     256
#define HH     128          // NH/2
#define CHUNK  64           // L: timesteps per chunk
#define NCHUNK 64           // T / CHUNK
#define NROWS  (T_LEN * NB) // 131072

// ---------------- scratch (device globals; no allocations allowed) ----------
__device__ float  g_X[T_LEN * NB * NH];                 // local-scan results (128 MiB)
__device__ float2 g_s[NCHUNK * NB * HH];                // per-chunk local end states
__device__ float2 g_S[NCHUNK * NB * HH];                // carry state entering each chunk
__device__ float2 g_P[CHUNK * HH];                      // P[k][h] = lambda_h^(k+1)
__device__ float2 g_lam[HH];                            // lambda
__device__ float  g_x0[NB * NH];                        // initial projected state

// ---------------- f32x2 helpers (sm_103a packed fp32 pipe) ------------------
__device__ __forceinline__ unsigned long long pack2(float lo, float hi) {
    unsigned long long d;
    asm("mov.b64 %0, {%1, %2};" : "=l"(d) : "f"(lo), "f"(hi));
    return d;
}
__device__ __forceinline__ void unpack2(unsigned long long v, float& lo, float& hi) {
    asm("mov.b64 {%0, %1}, %2;" : "=f"(lo), "=f"(hi) : "l"(v));
}
__device__ __forceinline__ unsigned long long fma2(unsigned long long a,
                                                   unsigned long long b,
                                                   unsigned long long c) {
    unsigned long long d;
    asm("fma.rn.f32x2 %0, %1, %2, %3;" : "=l"(d) : "l"(a), "l"(b), "l"(c));
    return d;
}

// ---------------- K1a: lambda + power table ---------------------------------
__global__ void k_init_lambda(const float* __restrict__ lre,
                              const float* __restrict__ lim) {
    int h = threadIdx.x;            // 128 threads
    float ar = fabsf(lre[h]);
    float th = 1.5707963267948966f * lim[h];
    float r  = expf(-ar);
    float sn, cs;
    sincosf(th, &sn, &cs);
    g_lam[h] = make_float2(r * cs, r * sn);
    #pragma unroll 4
    for (int k = 0; k < CHUNK; k++) {
        float kk  = (float)(k + 1);
        float rho = expf(-kk * ar);
        float s2, c2;
        sincosf(kk * th, &s2, &c2);
        g_P[k * HH + h] = make_float2(rho * c2, rho * s2);
    }
}

// ---------------- K1b: x0 = y0 @ W_y2x^T + b_y2x ----------------------------
__global__ void k_init_x0(const float* __restrict__ y0,
                          const float* __restrict__ W,      // [NH][NY]
                          const float* __restrict__ bias) {
    __shared__ float ys[NY];
    int b = blockIdx.x;     // 32 blocks
    int j = threadIdx.x;    // 256 threads
    if (j < NY) ys[j] = y0[b * NY + j];
    __syncthreads();
    float acc = bias[j];
    #pragma unroll
    for (int y = 0; y < NY; y++) acc = fmaf(W[j * NY + y], ys[y], acc);
    g_x0[b * NH + j] = acc;
}

// ---------------- K2: fused Bu GEMV + chunk-local scan ----------------------
// grid (NCHUNK, NB), 128 threads (one per complex channel h)
__global__ __launch_bounds__(128, 3)
void k_scan(const float* __restrict__ U,       // [T][NB][NU]
            const float* __restrict__ B) {     // [NH][NU]
    __shared__ unsigned long long Us2[CHUNK * NU];   // (u,u) packed, 32 KB
    int c = blockIdx.x;
    int b = blockIdx.y;
    int h = threadIdx.x;

    // B rows for (h, h+128) packed into registers: 64 x f32x2
    unsigned long long breg[NU];
    #pragma unroll
    for (int u = 0; u < NU; u++)
        breg[u] = pack2(__ldg(&B[h * NU + u]), __ldg(&B[(h + HH) * NU + u]));

    // stage this chunk's U tile, duplicated-packed for f32x2 broadcast
    int t0 = c * CHUNK;
    for (int i = h; i < CHUNK * NU; i += 128) {
        int tt = i >> 6, u = i & 63;
        float v = U[((t0 + tt) * NB + b) * NU + u];
        Us2[i] = pack2(v, v);
    }
    __syncthreads();

    float2 lam = g_lam[h];
    float zr = 0.f, zi = 0.f;
    for (int tt = 0; tt < CHUNK; tt++) {
        unsigned long long acc = 0ull;   // (0.0f, 0.0f)
        const unsigned long long* uv = &Us2[tt * NU];
        #pragma unroll
        for (int u = 0; u < NU; u++)
            acc = fma2(breg[u], uv[u], acc);
        float a, bb;
        unpack2(acc, a, bb);
        float nzr = fmaf(lam.x, zr, fmaf(-lam.y, zi, a));
        float nzi = fmaf(lam.y, zr, fmaf( lam.x, zi, bb));
        zr = nzr; zi = nzi;
        int R = (t0 + tt) * NB + b;
        g_X[R * NH + h]      = zr;
        g_X[R * NH + HH + h] = zi;
    }
    g_s[(c * NB + b) * HH + h] = make_float2(zr, zi);
}

// ---------------- K3: sequential combine across chunks ----------------------
// grid NB blocks, 128 threads
__global__ void k_combine() {
    int b = blockIdx.x;
    int h = threadIdx.x;
    float2 lamL = g_P[(CHUNK - 1) * HH + h];   // lambda^L
    float Sr = g_x0[b * NH + h];
    float Si = g_x0[b * NH + HH + h];
    for (int c = 0; c < NCHUNK; c++) {
        g_S[(c * NB + b) * HH + h] = make_float2(Sr, Si);
        float2 s = g_s[(c * NB + b) * HH + h];
        float nr = fmaf(lamL.x, Sr, fmaf(-lamL.y, Si, s.x));
        float ni = fmaf(lamL.y, Sr, fmaf( lamL.x, Si, s.y));
        Sr = nr; Si = ni;
    }
}

// ---------------- K5: carry fix-up + output GEMM ----------------------------
// block: 256 threads = 16 y-quads x 16 row-groups (2 rows each) -> 32-row subtile
// block covers 128 rows (4 subtiles); grid 1024 blocks
#define ROWS_PER_BLOCK 128
#define SUB_ROWS 32
__global__ __launch_bounds__(256, 1)
void k_out(const float* __restrict__ Wx2y,     // [NY][NH]
           const float* __restrict__ bias,     // [NY]
           float* __restrict__ Y) {            // [T][NB][NY]
    extern __shared__ unsigned long long smem[];
    unsigned long long* Ws = smem;               // [NH][32] packed y-pairs, 64 KB
    unsigned long long* Xs = smem + NH * 32;     // [SUB_ROWS][NH] (x,x) packed, 64 KB

    int tid = threadIdx.x;
    // Ws[h][p] = (W[2p][h], W[2p+1][h])
    for (int i = tid; i < NH * 32; i += 256) {
        int h = i >> 5, p = i & 31;
        Ws[h * 32 + p] = pack2(Wx2y[(2 * p) * NH + h], Wx2y[(2 * p + 1) * NH + h]);
    }
    __syncthreads();

    int yq = tid & 15;        // y-quad: y = 4*yq .. 4*yq+3
    int rg = tid >> 4;        // row-group within subtile: rows 2*rg, 2*rg+1
    float b0 = bias[yq * 4 + 0], b1 = bias[yq * 4 + 1];
    float b2 = bias[yq * 4 + 2], b3 = bias[yq * 4 + 3];
    int block_row0 = blockIdx.x * ROWS_PER_BLOCK;

    for (int sub = 0; sub < ROWS_PER_BLOCK / SUB_ROWS; sub++) {
        int row0 = block_row0 + sub * SUB_ROWS;

        // build X subtile with carry fix-up fused
        for (int i = tid; i < SUB_ROWS * NH; i += 256) {
            int rs = i >> 8, h = i & 255;
            int R  = row0 + rs;
            int t  = R >> 5;           // /NB
            int bb = R & 31;
            int c  = t >> 6;           // /CHUNK
            int tl = t & 63;
            int hp = h & 127;
            float2 P = g_P[tl * HH + hp];
            float2 S = g_S[(c * NB + bb) * HH + hp];
            float  x = g_X[R * NH + h];
            if (h < HH) x = fmaf(P.x, S.x, fmaf(-P.y, S.y, x));
            else        x = fmaf(P.y, S.x, fmaf( P.x, S.y, x));
            Xs[rs * NH + h] = pack2(x, x);
        }
        __syncthreads();

        unsigned long long a00 = pack2(b0, b1), a01 = pack2(b2, b3);
        unsigned long long a10 = pack2(b0, b1), a11 = pack2(b2, b3);
        const unsigned long long* x0p = &Xs[(rg * 2) * NH];
        const unsigned long long* x1p = &Xs[(rg * 2 + 1) * NH];
        #pragma unroll 8
        for (int h = 0; h < NH; h++) {
            ulonglong2 w2 = *(const ulonglong2*)(Ws + h * 32 + yq * 2);
            unsigned long long xv0 = x0p[h];
            unsigned long long xv1 = x1p[h];
            a00 = fma2(xv0, w2.x, a00);
            a01 = fma2(xv0, w2.y, a01);
            a10 = fma2(xv1, w2.x, a10);
            a11 = fma2(xv1, w2.y, a11);
        }
        int R0 = row0 + rg * 2;
        float o0, o1, o2, o3;
        unpack2(a00, o0, o1); unpack2(a01, o2, o3);
        *(float4*)(Y + R0 * NY + yq * 4) = make_float4(o0, o1, o2, o3);
        unpack2(a10, o0, o1); unpack2(a11, o2, o3);
        *(float4*)(Y + (R0 + 1) * NY + yq * 4) = make_float4(o0, o1, o2, o3);
        __syncthreads();
    }
}

// ---------------- launch ----------------------------------------------------
extern "C" void kernel_launch(void* const* d_in, const int* in_sizes, int n_in,
                              void* d_out, int out_size) {
    const float* y0   = (const float*)d_in[0];
    const float* U    = (const float*)d_in[1];
    const float* lre  = (const float*)d_in[2];
    const float* lim  = (const float*)d_in[3];
    const float* B    = (const float*)d_in[4];
    const float* Wy2x = (const float*)d_in[5];
    const float* by2x = (const float*)d_in[6];
    const float* Wx2y = (const float*)d_in[7];
    const float* bx2y = (const float*)d_in[8];
    float* Y = (float*)d_out;

    k_init_lambda<<<1, 128>>>(lre, lim);
    k_init_x0<<<NB, 256>>>(y0, Wy2x, by2x);
    k_scan<<<dim3(NCHUNK, NB), 128>>>(U, B);
    k_combine<<<NB, 128>>>();

    static_assert(NH * 32 * 8 * 2 == 131072, "smem layout");
    cudaFuncSetAttribute(k_out, cudaFuncAttributeMaxDynamicSharedMemorySize, 131072);
    k_out<<<NROWS / ROWS_PER_BLOCK, 256, 131072>>>(Wx2y, bx2y, Y);
}

// round 2
// speedup vs baseline: 1.2106x; 1.2106x over previous
#include <cuda_runtime.h>
#include <cuda_bf16.h>

// Problem constants
#define T_LEN  4096
#define NB     32
#define NU     64
#define NY     64
#define NH     256
#define HH     128          // NH/2
#define CHUNK  64           // timesteps per chunk
#define NCHUNK 64           // T / CHUNK
#define NROWS  (T_LEN * NB) // 131072

// ---------------- scratch (device globals; no allocations allowed) ----------
__device__ float2 g_X2[T_LEN * NB * HH];                // local-scan (zr,zi) pairs, 128 MiB
__device__ float2 g_s[NCHUNK * NB * HH];                // per-chunk local end states
__device__ float2 g_S[NCHUNK * NB * HH];                // carry state entering each chunk
__device__ float2 g_P[CHUNK * HH];                      // P[k][h] = lambda_h^(k+1)
__device__ float2 g_lam[HH];                            // lambda
__device__ float  g_x0[NB * NH];                        // initial projected state

// ---------------- f32x2 helpers (sm_103a packed fp32 pipe) ------------------
__device__ __forceinline__ unsigned long long pack2(float lo, float hi) {
    unsigned long long d;
    asm("mov.b64 %0, {%1, %2};" : "=l"(d) : "f"(lo), "f"(hi));
    return d;
}
__device__ __forceinline__ unsigned long long dup2(float v) {
    unsigned long long d;
    asm("mov.b64 %0, {%1, %1};" : "=l"(d) : "f"(v));
    return d;
}
__device__ __forceinline__ void unpack2(unsigned long long v, float& lo, float& hi) {
    asm("mov.b64 {%0, %1}, %2;" : "=f"(lo), "=f"(hi) : "l"(v));
}
__device__ __forceinline__ unsigned long long fma2(unsigned long long a,
                                                   unsigned long long b,
                                                   unsigned long long c) {
    unsigned long long d;
    asm("fma.rn.f32x2 %0, %1, %2, %3;" : "=l"(d) : "l"(a), "l"(b), "l"(c));
    return d;
}
__device__ __forceinline__ unsigned long long add2(unsigned long long a,
                                                   unsigned long long b) {
    unsigned long long d;
    asm("add.rn.f32x2 %0, %1, %2;" : "=l"(d) : "l"(a), "l"(b));
    return d;
}

// ---------------- K1a: lambda + power table ---------------------------------
__global__ void k_init_lambda(const float* __restrict__ lre,
                              const float* __restrict__ lim) {
    int h = threadIdx.x;            // 128 threads
    float ar = fabsf(lre[h]);
    float th = 1.5707963267948966f * lim[h];
    float r  = expf(-ar);
    float sn, cs;
    sincosf(th, &sn, &cs);
    g_lam[h] = make_float2(r * cs, r * sn);
    #pragma unroll 4
    for (int k = 0; k < CHUNK; k++) {
        float kk  = (float)(k + 1);
        float rho = expf(-kk * ar);
        float s2, c2;
        sincosf(kk * th, &s2, &c2);
        g_P[k * HH + h] = make_float2(rho * c2, rho * s2);
    }
}

// ---------------- K1b: x0 = y0 @ W_y2x^T + b_y2x ----------------------------
__global__ void k_init_x0(const float* __restrict__ y0,
                          const float* __restrict__ W,      // [NH][NY]
                          const float* __restrict__ bias) {
    __shared__ float ys[NY];
    int b = blockIdx.x;     // 32 blocks
    int j = threadIdx.x;    // 256 threads
    if (j < NY) ys[j] = y0[b * NY + j];
    __syncthreads();
    float acc = bias[j];
    #pragma unroll
    for (int y = 0; y < NY; y++) acc = fmaf(W[j * NY + y], ys[y], acc);
    g_x0[b * NH + j] = acc;
}

// ---------------- K2: fused Bu GEMV + chunk-local scan ----------------------
// grid (NCHUNK, NB), 128 threads (one per complex channel h)
__global__ __launch_bounds__(128, 3)
void k_scan(const float* __restrict__ U,       // [T][NB][NU]
            const float* __restrict__ B) {     // [NH][NU]
    __shared__ __align__(16) unsigned long long Us2[CHUNK * NU];   // (u,u) packed, 32 KB
    int c = blockIdx.x;
    int b = blockIdx.y;
    int h = threadIdx.x;

    // B rows for (h, h+128) packed into registers: 64 x f32x2
    unsigned long long breg[NU];
    #pragma unroll
    for (int u = 0; u < NU; u++)
        breg[u] = pack2(__ldg(&B[h * NU + u]), __ldg(&B[(h + HH) * NU + u]));

    // stage this chunk's U tile, duplicated-packed for f32x2 broadcast
    int t0 = c * CHUNK;
    for (int i = h; i < CHUNK * NU; i += 128) {
        int tt = i >> 6, u = i & 63;
        float v = U[((t0 + tt) * NB + b) * NU + u];
        Us2[i] = pack2(v, v);
    }
    __syncthreads();

    float2 lam = g_lam[h];
    float zr = 0.f, zi = 0.f;
    #pragma unroll 1
    for (int tt = 0; tt < CHUNK; tt++) {
        const ulonglong2* uv = (const ulonglong2*)(Us2 + tt * NU);
        unsigned long long a0 = 0ull, a1 = 0ull, a2 = 0ull, a3 = 0ull;
        #pragma unroll
        for (int q = 0; q < 16; q++) {
            ulonglong2 v0 = uv[2 * q];
            ulonglong2 v1 = uv[2 * q + 1];
            a0 = fma2(breg[4 * q + 0], v0.x, a0);
            a1 = fma2(breg[4 * q + 1], v0.y, a1);
            a2 = fma2(breg[4 * q + 2], v1.x, a2);
            a3 = fma2(breg[4 * q + 3], v1.y, a3);
        }
        unsigned long long s = add2(add2(a0, a1), add2(a2, a3));
        float a, bb;
        unpack2(s, a, bb);
        float nzr = fmaf(lam.x, zr, fmaf(-lam.y, zi, a));
        float nzi = fmaf(lam.y, zr, fmaf( lam.x, zi, bb));
        zr = nzr; zi = nzi;
        int R = (t0 + tt) * NB + b;
        g_X2[R * HH + h] = make_float2(zr, zi);
    }
    g_s[(c * NB + b) * HH + h] = make_float2(zr, zi);
}

// ---------------- K3: sequential combine across chunks (prefetched) ---------
// grid NB blocks, 128 threads
__global__ void k_combine() {
    int b = blockIdx.x;
    int h = threadIdx.x;
    float2 lamL = g_P[(CHUNK - 1) * HH + h];   // lambda^L
    float Sr = g_x0[b * NH + h];
    float Si = g_x0[b * NH + HH + h];
    float2 buf[8];
    #pragma unroll
    for (int j = 0; j < 8; j++) buf[j] = g_s[(j * NB + b) * HH + h];
    #pragma unroll 1
    for (int c0 = 0; c0 < NCHUNK; c0 += 8) {
        float2 nxt[8];
        if (c0 + 8 < NCHUNK) {
            #pragma unroll
            for (int j = 0; j < 8; j++) nxt[j] = g_s[((c0 + 8 + j) * NB + b) * HH + h];
        }
        #pragma unroll
        for (int j = 0; j < 8; j++) {
            g_S[((c0 + j) * NB + b) * HH + h] = make_float2(Sr, Si);
            float2 s = buf[j];
            float nr = fmaf(lamL.x, Sr, fmaf(-lamL.y, Si, s.x));
            float ni = fmaf(lamL.y, Sr, fmaf( lamL.x, Si, s.y));
            Sr = nr; Si = ni;
        }
        #pragma unroll
        for (int j = 0; j < 8; j++) buf[j] = nxt[j];
    }
}

// ---------------- K5: carry fix-up + output GEMM ----------------------------
// 256 threads: 8 col-groups (8 y each) x 32 row-groups (4 rows each) -> 128 rows
#define ROWS_PER_BLOCK 128
__global__ __launch_bounds__(256, 1)
void k_out(const float* __restrict__ Wx2y,     // [NY][NH]
           const float* __restrict__ bias,     // [NY]
           float* __restrict__ Y) {            // [T][NB][NY]
    extern __shared__ __align__(16) unsigned long long smem[];
    unsigned long long* Ws = smem;                       // [NH][32] y-pairs, 64 KB
    float* Xs = (float*)(smem + NH * 32);                // [128][NH] plain, 128 KB

    int tid = threadIdx.x;
    // Ws[h][p] = (W[2p][h], W[2p+1][h])
    for (int i = tid; i < NH * 32; i += 256) {
        int h = i >> 5, p = i & 31;
        Ws[h * 32 + p] = pack2(Wx2y[(2 * p) * NH + h], Wx2y[(2 * p + 1) * NH + h]);
    }

    int row0 = blockIdx.x * ROWS_PER_BLOCK;

    // Build X tile with carry fix-up fused (coalesced float2 reads)
    for (int i = tid; i < ROWS_PER_BLOCK * HH; i += 256) {
        int rs = i >> 7, hp = i & 127;
        int R  = row0 + rs;
        int t  = R >> 5;           // / NB
        int bb = R & 31;
        int c  = t >> 6;           // / CHUNK
        int tl = t & 63;
        float2 x2 = g_X2[R * HH + hp];
        float2 P  = g_P[tl * HH + hp];
        float2 S  = g_S[(c * NB + bb) * HH + hp];
        float xr = fmaf(P.x, S.x, fmaf(-P.y, S.y, x2.x));
        float xi = fmaf(P.y, S.x, fmaf( P.x, S.y, x2.y));
        Xs[rs * NH + hp]      = xr;
        Xs[rs * NH + HH + hp] = xi;
    }
    __syncthreads();

    int cg = tid & 7;         // y columns 8*cg .. 8*cg+7 (pairs cg*4 .. cg*4+3)
    int rg = tid >> 3;        // rows 4*rg .. 4*rg+3

    unsigned long long acc[4][4];
    #pragma unroll
    for (int r = 0; r < 4; r++)
        #pragma unroll
        for (int q = 0; q < 4; q++)
            acc[r][q] = pack2(bias[8 * cg + 2 * q], bias[8 * cg + 2 * q + 1]);

    const float* x0p = &Xs[(rg * 4 + 0) * NH];
    const float* x1p = &Xs[(rg * 4 + 1) * NH];
    const float* x2p = &Xs[(rg * 4 + 2) * NH];
    const float* x3p = &Xs[(rg * 4 + 3) * NH];

    #pragma unroll 4
    for (int hh = 0; hh < NH; hh++) {
        ulonglong2 w01 = *(const ulonglong2*)(Ws + hh * 32 + cg * 4);
        ulonglong2 w23 = *(const ulonglong2*)(Ws + hh * 32 + cg * 4 + 2);
        unsigned long long x0 = dup2(x0p[hh]);
        unsigned long long x1 = dup2(x1p[hh]);
        unsigned long long x2 = dup2(x2p[hh]);
        unsigned long long x3 = dup2(x3p[hh]);
        acc[0][0] = fma2(x0, w01.x, acc[0][0]);
        acc[0][1] = fma2(x0, w01.y, acc[0][1]);
        acc[0][2] = fma2(x0, w23.x, acc[0][2]);
        acc[0][3] = fma2(x0, w23.y, acc[0][3]);
        acc[1][0] = fma2(x1, w01.x, acc[1][0]);
        acc[1][1] = fma2(x1, w01.y, acc[1][1]);
        acc[1][2] = fma2(x1, w23.x, acc[1][2]);
        acc[1][3] = fma2(x1, w23.y, acc[1][3]);
        acc[2][0] = fma2(x2, w01.x, acc[2][0]);
        acc[2][1] = fma2(x2, w01.y, acc[2][1]);
        acc[2][2] = fma2(x2, w23.x, acc[2][2]);
        acc[2][3] = fma2(x2, w23.y, acc[2][3]);
        acc[3][0] = fma2(x3, w01.x, acc[3][0]);
        acc[3][1] = fma2(x3, w01.y, acc[3][1]);
        acc[3][2] = fma2(x3, w23.x, acc[3][2]);
        acc[3][3] = fma2(x3, w23.y, acc[3][3]);
    }

    #pragma unroll
    for (int r = 0; r < 4; r++) {
        int R = row0 + rg * 4 + r;
        float o0, o1, o2, o3, o4, o5, o6, o7;
        unpack2(acc[r][0], o0, o1); unpack2(acc[r][1], o2, o3);
        unpack2(acc[r][2], o4, o5); unpack2(acc[r][3], o6, o7);
        *(float4*)(Y + R * NY + 8 * cg)     = make_float4(o0, o1, o2, o3);
        *(float4*)(Y + R * NY + 8 * cg + 4) = make_float4(o4, o5, o6, o7);
    }
}

// ---------------- launch ----------------------------------------------------
extern "C" void kernel_launch(void* const* d_in, const int* in_sizes, int n_in,
                              void* d_out, int out_size) {
    const float* y0   = (const float*)d_in[0];
    const float* U    = (const float*)d_in[1];
    const float* lre  = (const float*)d_in[2];
    const float* lim  = (const float*)d_in[3];
    const float* B    = (const float*)d_in[4];
    const float* Wy2x = (const float*)d_in[5];
    const float* by2x = (const float*)d_in[6];
    const float* Wx2y = (const float*)d_in[7];
    const float* bx2y = (const float*)d_in[8];
    float* Y = (float*)d_out;

    k_init_lambda<<<1, 128>>>(lre, lim);
    k_init_x0<<<NB, 256>>>(y0, Wy2x, by2x);
    k_scan<<<dim3(NCHUNK, NB), 128>>>(U, B);
    k_combine<<<NB, 128>>>();

    const int smem_out = NH * 32 * 8 + ROWS_PER_BLOCK * NH * 4;  // 64KB + 128KB
    cudaFuncSetAttribute(k_out, cudaFuncAttributeMaxDynamicSharedMemorySize, smem_out);
    k_out<<<NROWS / ROWS_PER_BLOCK, 256, smem_out>>>(Wx2y, bx2y, Y);
}

// round 4
// speedup vs baseline: 2.2030x; 1.8198x over previous
#include <cuda_runtime.h>
#include <cuda_bf16.h>
#include <cstdint>

// Problem constants
#define T_LEN  4096
#define NB     32
#define NU     64
#define NY     64
#define NH     256
#define HH     128
#define CHUNK  64
#define NCHUNK 64
#define NROWS  (T_LEN * NB)

// ---------------- scratch globals -------------------------------------------
__device__ float2 g_X2[T_LEN * NB * HH];                // local-scan (zr,zi), 128 MiB
__device__ float2 g_s[NCHUNK * NB * HH];
__device__ float2 g_S[NCHUNK * NB * HH];
__device__ float2 g_P[CHUNK * HH];                      // lambda^(k+1)
__device__ float2 g_lam[HH];
__device__ float  g_x0[NB * NH];
// B packed: [h=256][pitch 136] bf16, hi at k, lo at 64+k  -> 69632 B
__device__ __align__(16) uint8_t g_B1p[69632];
// W packed: [y=64][pitch 520] bf16, hi at k, lo at 256+k  -> 66560 B
__device__ __align__(16) uint8_t g_Wp[66560];

// ---------------- helpers ----------------------------------------------------
__device__ __forceinline__ uint32_t smem_u32(const void* p) {
    uint32_t a;
    asm("{ .reg .u64 t; cvta.to.shared.u64 t, %1; cvt.u32.u64 %0, t; }" : "=r"(a) : "l"(p));
    return a;
}
__device__ __forceinline__ void ldsm4(uint32_t* r, uint32_t addr) {
    asm volatile("ldmatrix.sync.aligned.m8n8.x4.shared.b16 {%0,%1,%2,%3}, [%4];"
                 : "=r"(r[0]), "=r"(r[1]), "=r"(r[2]), "=r"(r[3]) : "r"(addr));
}
__device__ __forceinline__ void mma_bf16(float* d, const uint32_t* a,
                                         uint32_t b0, uint32_t b1) {
    asm volatile("mma.sync.aligned.m16n8k16.row.col.f32.bf16.bf16.f32 "
                 "{%0,%1,%2,%3}, {%4,%5,%6,%7}, {%8,%9}, {%0,%1,%2,%3};"
                 : "+f"(d[0]), "+f"(d[1]), "+f"(d[2]), "+f"(d[3])
                 : "r"(a[0]), "r"(a[1]), "r"(a[2]), "r"(a[3]), "r"(b0), "r"(b1));
}
__device__ __forceinline__ void split_bf16(float x, __nv_bfloat16& hi, __nv_bfloat16& lo) {
    hi = __float2bfloat16(x);
    lo = __float2bfloat16(x - __bfloat162float(hi));
}

// ---------------- K1a: lambda + power table ---------------------------------
__global__ void k_init_lambda(const float* __restrict__ lre,
                              const float* __restrict__ lim) {
    int h = threadIdx.x;            // 128
    float ar = fabsf(lre[h]);
    float th = 1.5707963267948966f * lim[h];
    float r  = expf(-ar);
    float sn, cs;
    sincosf(th, &sn, &cs);
    g_lam[h] = make_float2(r * cs, r * sn);
    #pragma unroll 4
    for (int k = 0; k < CHUNK; k++) {
        float kk  = (float)(k + 1);
        float rho = expf(-kk * ar);
        float s2, c2;
        sincosf(kk * th, &s2, &c2);
        g_P[k * HH + h] = make_float2(rho * c2, rho * s2);
    }
}

// ---------------- K1b: x0 = y0 @ W_y2x^T + b_y2x ----------------------------
__global__ void k_init_x0(const float* __restrict__ y0,
                          const float* __restrict__ W,
                          const float* __restrict__ bias) {
    __shared__ float ys[NY];
    int b = blockIdx.x;
    int j = threadIdx.x;   // 256
    if (j < NY) ys[j] = y0[b * NY + j];
    __syncthreads();
    float acc = bias[j];
    #pragma unroll
    for (int y = 0; y < NY; y++) acc = fmaf(W[j * NY + y], ys[y], acc);
    g_x0[b * NH + j] = acc;
}

// ---------------- K1c: pre-pack B and W as bf16 hi|lo ------------------------
__global__ void k_pack(const float* __restrict__ B,        // [NH][NU]
                       const float* __restrict__ Wx2y) {   // [NY][NH]
    int tid = threadIdx.x;   // 256
    __nv_bfloat16* bp = (__nv_bfloat16*)g_B1p;
    for (int i = tid; i < NH * NU; i += 256) {
        int h = i >> 6, u = i & 63;
        __nv_bfloat16 hi, lo;
        split_bf16(B[i], hi, lo);
        bp[h * 136 + u]      = hi;
        bp[h * 136 + 64 + u] = lo;
    }
    __nv_bfloat16* wp = (__nv_bfloat16*)g_Wp;
    for (int i = tid; i < NY * NH; i += 256) {
        int y = i >> 8, k = i & 255;
        __nv_bfloat16 hi, lo;
        split_bf16(Wx2y[i], hi, lo);
        wp[y * 520 + k]       = hi;
        wp[y * 520 + 256 + k] = lo;
    }
}

// ---------------- K_A: HMMA Bu GEMM + chunk-local scan -----------------------
// grid (NCHUNK, NB), 256 threads. M = 64 (tl), N = 256 (h), K = 64 (u) x 3 terms.
#define A1_OFF 1024
#define B1_OFF (A1_OFF + 64 * 136 * 2)        // 18432
#define SMEM_A_TOTAL (B1_OFF + 69632)         // 88064
#define XS_OFF 1024
#define XPITCH 69                              // floats; 256*69*4 = 70656 < 69632+17408

__global__ __launch_bounds__(256, 2)
void k_fusedA(const float* __restrict__ U) {
    extern __shared__ char smem[];
    uint32_t sb = smem_u32(smem);
    int tid = threadIdx.x, wid = tid >> 5, lane = tid & 31;
    int c = blockIdx.x, b = blockIdx.y;
    int t0 = c * CHUNK;

    // stage packed B (straight copy; L2-resident)
    {
        const uint4* gb = (const uint4*)g_B1p;
        uint4* sB = (uint4*)(smem + B1_OFF);
        for (int i = tid; i < 69632 / 16; i += 256) sB[i] = gb[i];
    }
    // convert U tile -> A1 [tl=64][136]: hi at u, lo at 64+u
    {
        __nv_bfloat16* ap = (__nv_bfloat16*)(smem + A1_OFF);
        #pragma unroll 4
        for (int i = tid; i < CHUNK * NU; i += 256) {
            int tl = i >> 6, u = i & 63;
            float x = U[((t0 + tl) * NB + b) * NU + u];
            __nv_bfloat16 hi, lo;
            split_bf16(x, hi, lo);
            ap[tl * 136 + u]      = hi;
            ap[tl * 136 + 64 + u] = lo;
        }
    }
    __syncthreads();

    // MMA: warp (wid&3) -> M rows 16*(wid&3); (wid>>2) -> N half
    int wm = (wid & 3) * 16;
    int wn = (wid >> 2) * 128;
    int lr = lane & 15, lc = lane >> 4;
    uint32_t a_base = sb + A1_OFF + (uint32_t)(wm + lr) * 272u + (uint32_t)lc * 16u;
    uint32_t b_base = sb + B1_OFF + (uint32_t)(wn + lr) * 272u + (uint32_t)lc * 16u;

    float d[16][4];
    #pragma unroll
    for (int n = 0; n < 16; n++)
        #pragma unroll
        for (int q = 0; q < 4; q++) d[n][q] = 0.f;

    #pragma unroll
    for (int t = 0; t < 3; t++) {
        const uint32_t aoff = (t == 1) ? 128u : 0u;   // +64 bf16 cols
        const uint32_t boff = (t == 2) ? 128u : 0u;
        #pragma unroll
        for (int ks = 0; ks < 4; ks++) {
            uint32_t a[4];
            ldsm4(a, a_base + aoff + ks * 32u);
            #pragma unroll
            for (int nt = 0; nt < 8; nt++) {
                uint32_t bf[4];
                ldsm4(bf, b_base + boff + ks * 32u + (uint32_t)nt * (16u * 272u));
                mma_bf16(d[2 * nt],     a, bf[0], bf[2]);
                mma_bf16(d[2 * nt + 1], a, bf[1], bf[3]);
            }
        }
    }
    __syncthreads();   // everyone done with A1/B1; reuse as Xs

    // write D transposed: Xs[h][r], pitch XPITCH
    float* Xs = (float*)(smem + XS_OFF);
    {
        int g = lane >> 2, tq = lane & 3;
        #pragma unroll
        for (int nt = 0; nt < 16; nt++) {
            int h  = wn + nt * 8 + tq * 2;
            int r0 = wm + g;
            Xs[h * XPITCH + r0]           = d[nt][0];
            Xs[(h + 1) * XPITCH + r0]     = d[nt][1];
            Xs[h * XPITCH + r0 + 8]       = d[nt][2];
            Xs[(h + 1) * XPITCH + r0 + 8] = d[nt][3];
        }
    }
    __syncthreads();

    // chunk-local scan + streamed store (threads 0..127, one complex channel)
    if (tid < HH) {
        int hp = tid;
        float2 lam = g_lam[hp];
        const float* rowR = Xs + hp * XPITCH;
        const float* rowI = Xs + (hp + HH) * XPITCH;
        float zr = 0.f, zi = 0.f;
        #pragma unroll 4
        for (int tl = 0; tl < CHUNK; tl++) {
            float a  = rowR[tl];
            float bi = rowI[tl];
            float nzr = fmaf(lam.x, zr, fmaf(-lam.y, zi, a));
            float nzi = fmaf(lam.y, zr, fmaf( lam.x, zi, bi));
            zr = nzr; zi = nzi;
            g_X2[((t0 + tl) * NB + b) * HH + hp] = make_float2(zr, zi);
        }
        g_s[(c * NB + b) * HH + hp] = make_float2(zr, zi);
    }
}

// ---------------- K3: combine across chunks (prefetched) ---------------------
__global__ void k_combine() {
    int b = blockIdx.x;
    int h = threadIdx.x;
    float2 lamL = g_P[(CHUNK - 1) * HH + h];
    float Sr = g_x0[b * NH + h];
    float Si = g_x0[b * NH + HH + h];
    float2 buf[8];
    #pragma unroll
    for (int j = 0; j < 8; j++) buf[j] = g_s[(j * NB + b) * HH + h];
    #pragma unroll 1
    for (int c0 = 0; c0 < NCHUNK; c0 += 8) {
        float2 nxt[8];
        if (c0 + 8 < NCHUNK) {
            #pragma unroll
            for (int j = 0; j < 8; j++) nxt[j] = g_s[((c0 + 8 + j) * NB + b) * HH + h];
        }
        #pragma unroll
        for (int j = 0; j < 8; j++) {
            g_S[((c0 + j) * NB + b) * HH + h] = make_float2(Sr, Si);
            float2 s = buf[j];
            float nr = fmaf(lamL.x, Sr, fmaf(-lamL.y, Si, s.x));
            float ni = fmaf(lamL.y, Sr, fmaf( lamL.x, Si, s.y));
            Sr = nr; Si = ni;
        }
        #pragma unroll
        for (int j = 0; j < 8; j++) buf[j] = nxt[j];
    }
}

// ---------------- K_B: fix-up + HMMA output GEMM -----------------------------
// grid 1024 blocks x 128 rows, 256 threads. M=128, N=64, K=256 x 3 terms.
#define W2_OFF 1024
#define A2_OFF (W2_OFF + 66560)               // 67584
#define SMEM_B_TOTAL (A2_OFF + 128 * 520 * 2) // 200704

__global__ __launch_bounds__(256, 1)
void k_outB(const float* __restrict__ bias, float* __restrict__ Y) {
    extern __shared__ char smem[];
    uint32_t sb = smem_u32(smem);
    int tid = threadIdx.x, wid = tid >> 5, lane = tid & 31;
    int row0 = blockIdx.x * 128;

    if (tid < NY) ((float*)smem)[tid] = bias[tid];
    {
        const uint4* gw = (const uint4*)g_Wp;
        uint4* sW = (uint4*)(smem + W2_OFF);
        for (int i = tid; i < 66560 / 16; i += 256) sW[i] = gw[i];
    }
    // fix-up + split -> A2 [rs=128][520]: real at hp, imag at 128+hp, lo at +256
    {
        __nv_bfloat16* ap = (__nv_bfloat16*)(smem + A2_OFF);
        #pragma unroll 4
        for (int i = tid; i < 128 * HH; i += 256) {
            int rs = i >> 7, hp = i & 127;
            int R  = row0 + rs;
            int t  = R >> 5, bb = R & 31;
            int cc = t >> 6, tl = t & 63;
            float2 x2 = g_X2[R * HH + hp];
            float2 P  = g_P[tl * HH + hp];
            float2 S  = g_S[(cc * NB + bb) * HH + hp];
            float xr = fmaf(P.x, S.x, fmaf(-P.y, S.y, x2.x));
            float xi = fmaf(P.y, S.x, fmaf( P.x, S.y, x2.y));
            __nv_bfloat16 hr, lr2, hi2, li2;
            split_bf16(xr, hr, lr2);
            split_bf16(xi, hi2, li2);
            __nv_bfloat16* row = ap + rs * 520;
            row[hp]            = hr;
            row[128 + hp]      = hi2;
            row[256 + hp]      = lr2;
            row[256 + 128 + hp]= li2;
        }
    }
    __syncthreads();

    int wm = wid * 16;
    int lr = lane & 15, lc = lane >> 4;
    uint32_t a_base = sb + A2_OFF + (uint32_t)(wm + lr) * 1040u + (uint32_t)lc * 16u;
    uint32_t b_base = sb + W2_OFF + (uint32_t)lr * 1040u + (uint32_t)lc * 16u;

    float d[8][4];
    #pragma unroll
    for (int n = 0; n < 8; n++)
        #pragma unroll
        for (int q = 0; q < 4; q++) d[n][q] = 0.f;

    #pragma unroll
    for (int t = 0; t < 3; t++) {
        const uint32_t aoff = (t == 1) ? 512u : 0u;   // +256 bf16 cols
        const uint32_t boff = (t == 2) ? 512u : 0u;
        #pragma unroll
        for (int ks = 0; ks < 16; ks++) {
            uint32_t a[4];
            ldsm4(a, a_base + aoff + ks * 32u);
            #pragma unroll
            for (int nt = 0; nt < 4; nt++) {
                uint32_t bf[4];
                ldsm4(bf, b_base + boff + ks * 32u + (uint32_t)nt * (16u * 1040u));
                mma_bf16(d[2 * nt],     a, bf[0], bf[2]);
                mma_bf16(d[2 * nt + 1], a, bf[1], bf[3]);
            }
        }
    }

    // epilogue: bias + store fragments
    {
        const float* bs = (const float*)smem;
        int g = lane >> 2, tq = lane & 3;
        int R0 = row0 + wm + g;
        #pragma unroll
        for (int nt = 0; nt < 8; nt++) {
            int col = nt * 8 + tq * 2;
            float b0 = bs[col], b1 = bs[col + 1];
            *(float2*)(Y + R0 * NY + col) =
                make_float2(d[nt][0] + b0, d[nt][1] + b1);
            *(float2*)(Y + (R0 + 8) * NY + col) =
                make_float2(d[nt][2] + b0, d[nt][3] + b1);
        }
    }
}

// ---------------- launch ----------------------------------------------------
extern "C" void kernel_launch(void* const* d_in, const int* in_sizes, int n_in,
                              void* d_out, int out_size) {
    const float* y0   = (const float*)d_in[0];
    const float* U    = (const float*)d_in[1];
    const float* lre  = (const float*)d_in[2];
    const float* lim  = (const float*)d_in[3];
    const float* B    = (const float*)d_in[4];
    const float* Wy2x = (const float*)d_in[5];
    const float* by2x = (const float*)d_in[6];
    const float* Wx2y = (const float*)d_in[7];
    const float* bx2y = (const float*)d_in[8];
    float* Y = (float*)d_out;

    k_init_lambda<<<1, 128>>>(lre, lim);
    k_init_x0<<<NB, 256>>>(y0, Wy2x, by2x);
    k_pack<<<1, 256>>>(B, Wx2y);

    cudaFuncSetAttribute(k_fusedA, cudaFuncAttributeMaxDynamicSharedMemorySize, SMEM_A_TOTAL);
    k_fusedA<<<dim3(NCHUNK, NB), 256, SMEM_A_TOTAL>>>(U);

    k_combine<<<NB, 128>>>();

    cudaFuncSetAttribute(k_outB, cudaFuncAttributeMaxDynamicSharedMemorySize, SMEM_B_TOTAL);
    k_outB<<<NROWS / 128, 256, SMEM_B_TOTAL>>>(bx2y, Y);
}